// round 10
// baseline (speedup 1.0000x reference)
#include <cuda_runtime.h>

#define A_    32
#define B_    32
#define KKA_  288
#define PS_   16
#define OH_   7
#define OW_   7
#define L_    49
#define NW_   6
#define NT_   192
#define W2SZ  (KKA_ * B_ * PS_)   // 147456 floats

typedef unsigned long long u64;

__device__ __constant__ float c_lam[3] = {0.0005f, 0.000975f, 0.00142625f};

// W transposed to [n][k(row)][o][4] so warp reads are coalesced
__device__ __align__(16) float W2g[W2SZ];

__global__ void wprep_kernel(const float* __restrict__ Wg) {
    int idx = blockIdx.x * 256 + threadIdx.x;
    if (idx < W2SZ) {
        int c = idx & 3;
        int o = (idx >> 2) & 31;
        int k = (idx >> 7) & 3;
        int n = idx >> 9;
        W2g[idx] = Wg[(n * 32 + o) * 16 + k * 4 + c];
    }
}

__device__ __forceinline__ u64 b2(float s) {
    u64 r; asm("mov.b64 %0,{%1,%1};" : "=l"(r) : "f"(s)); return r;
}
__device__ __forceinline__ u64 pk2(float x, float y) {
    u64 r; asm("mov.b64 %0,{%1,%2};" : "=l"(r) : "f"(x), "f"(y)); return r;
}
__device__ __forceinline__ u64 fma2(u64 a, u64 b, u64 c) {
    u64 d; asm("fma.rn.f32x2 %0,%1,%2,%3;" : "=l"(d) : "l"(a), "l"(b), "l"(c)); return d;
}
__device__ __forceinline__ u64 mul2(u64 a, u64 b) {
    u64 d; asm("mul.rn.f32x2 %0,%1,%2;" : "=l"(d) : "l"(a), "l"(b)); return d;
}
__device__ __forceinline__ u64 add2(u64 a, u64 b) {
    u64 d; asm("add.rn.f32x2 %0,%1,%2;" : "=l"(d) : "l"(a), "l"(b)); return d;
}
__device__ __forceinline__ void unpk(u64 a, float& x, float& y) {
    asm("mov.b64 {%0,%1},%2;" : "=f"(x), "=f"(y) : "l"(a));
}

__global__ void __launch_bounds__(NT_, 3)
convcaps_kernel(const float* __restrict__ a_in,
                const float* __restrict__ pose,
                const float* __restrict__ beta_u,
                const float* __restrict__ beta_a,
                float* __restrict__ out,
                int batch)
{
    __shared__ __align__(16) float pose_s[KKA_][PS_];   // [n][i*4+m]
    __shared__ float au_s[KKA_];
    __shared__ float S1s[PS_][B_];                      // [j][o]
    __shared__ float S2s[PS_][B_];
    __shared__ float rss[B_];
    __shared__ __align__(8) float c1s[8][B_][2];        // [jp][o][j&1] : -mu/sig
    __shared__ __align__(8) float c2s[8][B_][2];        // 0.5/sig
    __shared__ float lsg[PS_][B_];                      // log(sigma^2)
    __shared__ float c0s[PS_][B_];                      // 0.5*mu^2/sig
    __shared__ float base_s[B_];                        // per-o constant for ln_ap
    __shared__ float Mglob_s;                           // global softmax shift

    const int site = blockIdx.x;
    const int bb = site / L_;
    const int l  = site - bb * L_;
    const int oy = l / OW_, ox = l - oy * OW_;
    const int tid = threadIdx.x;
    const int wid = tid / 32, lane = tid & 31;
    const int aout_total = batch * B_ * L_;

    // ---- load pose window (288 x 16) and activations (288) ----
    for (int idx = tid; idx < KKA_ * PS_; idx += NT_) {
        int n = idx >> 4, s = idx & 15;
        int p = n >> 5, a = n & 31;
        int ki = p / 3, kj = p - 3 * ki;
        pose_s[n][s] = pose[((bb * 512 + a * 16 + s) * 16 + 2 * oy + ki) * 16 + 2 * ox + kj];
    }
    for (int n = tid; n < KKA_; n += NT_) {
        int p = n >> 5, a = n & 31;
        int ki = p / 3, kj = p - 3 * ki;
        au_s[n] = a_in[((bb * 32 + a) * 16 + 2 * oy + ki) * 16 + 2 * ox + kj];
    }
    __syncthreads();

    const u64* c1p = (const u64*)c1s;
    const u64* c2p = (const u64*)c2s;

    for (int it = 0; it < 3; ++it) {
        for (int idx = tid; idx < PS_ * B_; idx += NT_) {
            ((float*)S1s)[idx] = 0.0f;
            ((float*)S2s)[idx] = 0.0f;
        }
        if (tid < B_) rss[tid] = 0.0f;
        __syncthreads();

        u64 a1[8], a2[8];
        #pragma unroll
        for (int k = 0; k < 8; ++k) { a1[k] = 0ull; a2[k] = 0ull; }
        float rs = 0.0f;

        if (it == 0) {
            #pragma unroll 2
            for (int n = wid; n < KKA_; n += NW_) {
                const float4* wf = (const float4*)(W2g + n * 512);
                float4 q0 = wf[lane], q1 = wf[32 + lane], q2 = wf[64 + lane], q3 = wf[96 + lane];
                u64 w0a = pk2(q0.x, q0.y), w0b = pk2(q0.z, q0.w);
                u64 w1a = pk2(q1.x, q1.y), w1b = pk2(q1.z, q1.w);
                u64 w2a = pk2(q2.x, q2.y), w2b = pk2(q2.z, q2.w);
                u64 w3a = pk2(q3.x, q3.y), w3b = pk2(q3.z, q3.w);
                float au = au_s[n];
                u64 au2 = b2(au);
                rs += au;
                const float4* prp = (const float4*)pose_s[n];
                #pragma unroll
                for (int i = 0; i < 4; ++i) {
                    float4 pr = prp[i];
                    u64 v0, v1;
                    v0 = mul2(b2(pr.x), w0a); v0 = fma2(b2(pr.y), w1a, v0);
                    v0 = fma2(b2(pr.z), w2a, v0); v0 = fma2(b2(pr.w), w3a, v0);
                    v1 = mul2(b2(pr.x), w0b); v1 = fma2(b2(pr.y), w1b, v1);
                    v1 = fma2(b2(pr.z), w2b, v1); v1 = fma2(b2(pr.w), w3b, v1);
                    u64 u0 = mul2(au2, v0);
                    a1[2*i]   = add2(a1[2*i], u0);   a2[2*i]   = fma2(u0, v0, a2[2*i]);
                    u64 u1 = mul2(au2, v1);
                    a1[2*i+1] = add2(a1[2*i+1], u1); a2[2*i+1] = fma2(u1, v1, a2[2*i+1]);
                }
            }
        } else {
            const float bm = base_s[lane] - Mglob_s;   // base - Mglob folded
            // per-o coefficients in registers (invariant over n)
            u64 cc1[8], cc2[8];
            #pragma unroll
            for (int k = 0; k < 8; ++k) {
                cc1[k] = c1p[k * B_ + lane];
                cc2[k] = c2p[k * B_ + lane];
            }
            #pragma unroll 2
            for (int n = wid; n < KKA_; n += NW_) {
                const float4* wf = (const float4*)(W2g + n * 512);
                float4 q0 = wf[lane], q1 = wf[32 + lane], q2 = wf[64 + lane], q3 = wf[96 + lane];
                u64 w0a = pk2(q0.x, q0.y), w0b = pk2(q0.z, q0.w);
                u64 w1a = pk2(q1.x, q1.y), w1b = pk2(q1.z, q1.w);
                u64 w2a = pk2(q2.x, q2.y), w2b = pk2(q2.z, q2.w);
                u64 w3a = pk2(q3.x, q3.y), w3b = pk2(q3.z, q3.w);
                const float4* prp = (const float4*)pose_s[n];

                // compute all 16 votes, keep live across softmax
                u64 v[8];
                #pragma unroll
                for (int i = 0; i < 4; ++i) {
                    float4 pr = prp[i];
                    u64 v0, v1;
                    v0 = mul2(b2(pr.x), w0a); v0 = fma2(b2(pr.y), w1a, v0);
                    v0 = fma2(b2(pr.z), w2a, v0); v0 = fma2(b2(pr.w), w3a, v0);
                    v1 = mul2(b2(pr.x), w0b); v1 = fma2(b2(pr.y), w1b, v1);
                    v1 = fma2(b2(pr.z), w2b, v1); v1 = fma2(b2(pr.w), w3b, v1);
                    v[2*i] = v0; v[2*i+1] = v1;
                }

                // phase A: Mahalanobis, two parallel chains
                u64 accA = 0ull, accB = 0ull;
                #pragma unroll
                for (int k = 0; k < 8; k += 2) {
                    u64 va = v[k], vb = v[k+1];
                    accA = fma2(va, cc1[k], accA);
                    accA = fma2(mul2(va, va), cc2[k], accA);
                    accB = fma2(vb, cc1[k+1], accB);
                    accB = fma2(mul2(vb, vb), cc2[k+1], accB);
                }
                float ax, ay, bx, by;
                unpk(accA, ax, ay); unpk(accB, bx, by);
                float t = bm - ((ax + ay) + (bx + by));

                // softmax over o (lane = o), global shift
                float e = __expf(t);
                float s = e;
                #pragma unroll
                for (int d = 16; d; d >>= 1)
                    s += __shfl_xor_sync(0xffffffffu, s, d);
                s = fmaxf(s, 1e-37f);
                float ra = e * __fdividef(au_s[n], s);
                rs += ra;
                u64 ra2 = b2(ra);

                // phase B: accumulate moments with live v
                #pragma unroll
                for (int k = 0; k < 8; ++k) {
                    u64 u = mul2(ra2, v[k]);
                    a1[k] = add2(a1[k], u);
                    a2[k] = fma2(u, v[k], a2[k]);
                }
            }
        }

        #pragma unroll
        for (int k = 0; k < 8; ++k) {
            float x, y;
            unpk(a1[k], x, y);
            atomicAdd(&S1s[2*k][lane], x);
            atomicAdd(&S1s[2*k+1][lane], y);
            unpk(a2[k], x, y);
            atomicAdd(&S2s[2*k][lane], x);
            atomicAdd(&S2s[2*k+1][lane], y);
        }
        atomicAdd(&rss[lane], rs);
        __syncthreads();

        // ---- stage 2a: per (o,j) stats ----
        const bool last = (it == 2);
        for (int idx = tid; idx < PS_ * B_; idx += NT_) {
            int j = idx >> 5, o = idx & 31;
            float denom = rss[o] + 1e-12f;
            float m  = __fdividef(S1s[j][o], denom);
            float e2 = __fdividef(S2s[j][o], denom);
            float sig = fmaxf(e2 - m * m, 0.0f) + 1e-12f;
            lsg[j][o] = __logf(sig);
            if (last) {
                out[aout_total + ((bb * 512 + o * 16 + j) * OH_ + oy) * OW_ + ox] = m;
            } else {
                float inv = __fdividef(1.0f, sig);
                c1s[j >> 1][o][j & 1] = -m * inv;
                c2s[j >> 1][o][j & 1] = 0.5f * inv;
                c0s[j][o] = 0.5f * m * m * inv;
            }
        }
        __syncthreads();

        // ---- stage 2b: per-o activation (+ global softmax shift) ----
        if (tid < B_) {
            int o = tid;
            float SL = 0.0f, C0 = 0.0f;
            #pragma unroll
            for (int j = 0; j < PS_; ++j) { SL += lsg[j][o]; C0 += c0s[j][o]; }
            float cost = rss[o] * (16.0f * beta_u[o] + 0.5f * SL);
            float x = c_lam[it] * (beta_a[o] - cost);
            float a = 1.0f / (1.0f + __expf(-x));
            if (it == 2) {
                out[((bb * B_ + o) * OH_ + oy) * OW_ + ox] = a;
            } else {
                float base2 = __logf(a) - 0.5f * SL - 8.0f * 0.6086151514f;
                base_s[o] = base2 - C0;
                float mg = base2;
                #pragma unroll
                for (int d = 16; d; d >>= 1)
                    mg = fmaxf(mg, __shfl_xor_sync(0xffffffffu, mg, d));
                if (o == 0) Mglob_s = mg;
            }
        }
        __syncthreads();
    }
}

extern "C" void kernel_launch(void* const* d_in, const int* in_sizes, int n_in,
                              void* d_out, int out_size) {
    const float* a_in  = (const float*)d_in[0];
    const float* pose  = (const float*)d_in[1];
    const float* Wg    = (const float*)d_in[2];
    const float* bu    = (const float*)d_in[3];
    const float* ba    = (const float*)d_in[4];
    float* out = (float*)d_out;

    int batch = in_sizes[0] / (A_ * 16 * 16);   // 8
    int grid = batch * L_;                       // 392

    wprep_kernel<<<(W2SZ + 255) / 256, 256>>>(Wg);
    convcaps_kernel<<<grid, NT_>>>(a_in, pose, bu, ba, out, batch);
}

// round 11
// speedup vs baseline: 1.0536x; 1.0536x over previous
#include <cuda_runtime.h>

#define A_    32
#define B_    32
#define KKA_  288
#define PS_   16
#define OH_   7
#define OW_   7
#define L_    49
#define NW_   5
#define NT_   160
#define W2SZ  (KKA_ * B_ * PS_)   // 147456 floats

typedef unsigned long long u64;

__device__ __constant__ float c_lam[3] = {0.0005f, 0.000975f, 0.00142625f};

// W transposed to [n][k(row)][o][4] so warp reads are coalesced
__device__ __align__(16) float W2g[W2SZ];

__global__ void wprep_kernel(const float* __restrict__ Wg) {
    int idx = blockIdx.x * 256 + threadIdx.x;
    if (idx < W2SZ) {
        int c = idx & 3;
        int o = (idx >> 2) & 31;
        int k = (idx >> 7) & 3;
        int n = idx >> 9;
        W2g[idx] = Wg[(n * 32 + o) * 16 + k * 4 + c];
    }
}

__device__ __forceinline__ u64 b2(float s) {
    u64 r; asm("mov.b64 %0,{%1,%1};" : "=l"(r) : "f"(s)); return r;
}
__device__ __forceinline__ u64 pk2(float x, float y) {
    u64 r; asm("mov.b64 %0,{%1,%2};" : "=l"(r) : "f"(x), "f"(y)); return r;
}
__device__ __forceinline__ u64 fma2(u64 a, u64 b, u64 c) {
    u64 d; asm("fma.rn.f32x2 %0,%1,%2,%3;" : "=l"(d) : "l"(a), "l"(b), "l"(c)); return d;
}
__device__ __forceinline__ u64 mul2(u64 a, u64 b) {
    u64 d; asm("mul.rn.f32x2 %0,%1,%2;" : "=l"(d) : "l"(a), "l"(b)); return d;
}
__device__ __forceinline__ u64 add2(u64 a, u64 b) {
    u64 d; asm("add.rn.f32x2 %0,%1,%2;" : "=l"(d) : "l"(a), "l"(b)); return d;
}
__device__ __forceinline__ void unpk(u64 a, float& x, float& y) {
    asm("mov.b64 {%0,%1},%2;" : "=f"(x), "=f"(y) : "l"(a));
}

__global__ void __launch_bounds__(NT_, 3)
convcaps_kernel(const float* __restrict__ a_in,
                const float* __restrict__ pose,
                const float* __restrict__ beta_u,
                const float* __restrict__ beta_a,
                float* __restrict__ out,
                int batch)
{
    __shared__ __align__(16) float pose_s[KKA_][PS_];   // [n][i*4+m]
    __shared__ float au_s[KKA_];
    __shared__ float S1s[PS_][B_];                      // [j][o]
    __shared__ float S2s[PS_][B_];
    __shared__ float rss[B_];
    __shared__ __align__(8) float c1s[8][B_][2];        // [jp][o][j&1] : -mu/sig
    __shared__ __align__(8) float c2s[8][B_][2];        // 0.5/sig
    __shared__ float lsg[PS_][B_];                      // log(sigma^2)
    __shared__ float c0s[PS_][B_];                      // 0.5*mu^2/sig
    __shared__ float base_s[B_];                        // per-o constant for ln_ap
    __shared__ float Mglob_s;                           // global softmax shift

    const int site = blockIdx.x;
    const int bb = site / L_;
    const int l  = site - bb * L_;
    const int oy = l / OW_, ox = l - oy * OW_;
    const int tid = threadIdx.x;
    const int wid = tid / 32, lane = tid & 31;
    const int aout_total = batch * B_ * L_;

    // ---- load pose window (288 x 16) and activations (288) ----
    for (int idx = tid; idx < KKA_ * PS_; idx += NT_) {
        int n = idx >> 4, s = idx & 15;
        int p = n >> 5, a = n & 31;
        int ki = p / 3, kj = p - 3 * ki;
        pose_s[n][s] = pose[((bb * 512 + a * 16 + s) * 16 + 2 * oy + ki) * 16 + 2 * ox + kj];
    }
    for (int n = tid; n < KKA_; n += NT_) {
        int p = n >> 5, a = n & 31;
        int ki = p / 3, kj = p - 3 * ki;
        au_s[n] = a_in[((bb * 32 + a) * 16 + 2 * oy + ki) * 16 + 2 * ox + kj];
    }
    __syncthreads();

    const u64* c1p = (const u64*)c1s;
    const u64* c2p = (const u64*)c2s;

    for (int it = 0; it < 3; ++it) {
        for (int idx = tid; idx < PS_ * B_; idx += NT_) {
            ((float*)S1s)[idx] = 0.0f;
            ((float*)S2s)[idx] = 0.0f;
        }
        if (tid < B_) rss[tid] = 0.0f;
        __syncthreads();

        u64 a1[8], a2[8];
        #pragma unroll
        for (int k = 0; k < 8; ++k) { a1[k] = 0ull; a2[k] = 0ull; }
        float rs = 0.0f;

        if (it == 0) {
            #pragma unroll 2
            for (int n = wid; n < KKA_; n += NW_) {
                const float4* wf = (const float4*)(W2g + n * 512);
                float4 q0 = wf[lane], q1 = wf[32 + lane], q2 = wf[64 + lane], q3 = wf[96 + lane];
                u64 w0a = pk2(q0.x, q0.y), w0b = pk2(q0.z, q0.w);
                u64 w1a = pk2(q1.x, q1.y), w1b = pk2(q1.z, q1.w);
                u64 w2a = pk2(q2.x, q2.y), w2b = pk2(q2.z, q2.w);
                u64 w3a = pk2(q3.x, q3.y), w3b = pk2(q3.z, q3.w);
                float au = au_s[n];
                u64 au2 = b2(au);
                rs += au;
                const float4* prp = (const float4*)pose_s[n];
                #pragma unroll
                for (int i = 0; i < 4; ++i) {
                    float4 pr = prp[i];
                    u64 v0, v1;
                    v0 = mul2(b2(pr.x), w0a); v0 = fma2(b2(pr.y), w1a, v0);
                    v0 = fma2(b2(pr.z), w2a, v0); v0 = fma2(b2(pr.w), w3a, v0);
                    v1 = mul2(b2(pr.x), w0b); v1 = fma2(b2(pr.y), w1b, v1);
                    v1 = fma2(b2(pr.z), w2b, v1); v1 = fma2(b2(pr.w), w3b, v1);
                    u64 u0 = mul2(au2, v0);
                    a1[2*i]   = add2(a1[2*i], u0);   a2[2*i]   = fma2(u0, v0, a2[2*i]);
                    u64 u1 = mul2(au2, v1);
                    a1[2*i+1] = add2(a1[2*i+1], u1); a2[2*i+1] = fma2(u1, v1, a2[2*i+1]);
                }
            }
        } else {
            const float bm = base_s[lane] - Mglob_s;   // base - Mglob folded
            // per-o coefficients in registers (invariant over n)
            u64 cc1[8], cc2[8];
            #pragma unroll
            for (int k = 0; k < 8; ++k) {
                cc1[k] = c1p[k * B_ + lane];
                cc2[k] = c2p[k * B_ + lane];
            }
            #pragma unroll 2
            for (int n = wid; n < KKA_; n += NW_) {
                const float4* wf = (const float4*)(W2g + n * 512);
                float4 q0 = wf[lane], q1 = wf[32 + lane], q2 = wf[64 + lane], q3 = wf[96 + lane];
                u64 w0a = pk2(q0.x, q0.y), w0b = pk2(q0.z, q0.w);
                u64 w1a = pk2(q1.x, q1.y), w1b = pk2(q1.z, q1.w);
                u64 w2a = pk2(q2.x, q2.y), w2b = pk2(q2.z, q2.w);
                u64 w3a = pk2(q3.x, q3.y), w3b = pk2(q3.z, q3.w);
                const float4* prp = (const float4*)pose_s[n];

                // compute all 16 votes, keep live across softmax
                u64 v[8];
                #pragma unroll
                for (int i = 0; i < 4; ++i) {
                    float4 pr = prp[i];
                    u64 v0, v1;
                    v0 = mul2(b2(pr.x), w0a); v0 = fma2(b2(pr.y), w1a, v0);
                    v0 = fma2(b2(pr.z), w2a, v0); v0 = fma2(b2(pr.w), w3a, v0);
                    v1 = mul2(b2(pr.x), w0b); v1 = fma2(b2(pr.y), w1b, v1);
                    v1 = fma2(b2(pr.z), w2b, v1); v1 = fma2(b2(pr.w), w3b, v1);
                    v[2*i] = v0; v[2*i+1] = v1;
                }

                // phase A: Mahalanobis, two parallel chains
                u64 accA = 0ull, accB = 0ull;
                #pragma unroll
                for (int k = 0; k < 8; k += 2) {
                    u64 va = v[k], vb = v[k+1];
                    accA = fma2(va, cc1[k], accA);
                    accA = fma2(mul2(va, va), cc2[k], accA);
                    accB = fma2(vb, cc1[k+1], accB);
                    accB = fma2(mul2(vb, vb), cc2[k+1], accB);
                }
                float ax, ay, bx, by;
                unpk(accA, ax, ay); unpk(accB, bx, by);
                float t = bm - ((ax + ay) + (bx + by));

                // softmax over o (lane = o), global shift
                float e = __expf(t);
                float s = e;
                #pragma unroll
                for (int d = 16; d; d >>= 1)
                    s += __shfl_xor_sync(0xffffffffu, s, d);
                s = fmaxf(s, 1e-37f);
                float ra = e * __fdividef(au_s[n], s);
                rs += ra;
                u64 ra2 = b2(ra);

                // phase B: accumulate moments with live v
                #pragma unroll
                for (int k = 0; k < 8; ++k) {
                    u64 u = mul2(ra2, v[k]);
                    a1[k] = add2(a1[k], u);
                    a2[k] = fma2(u, v[k], a2[k]);
                }
            }
        }

        #pragma unroll
        for (int k = 0; k < 8; ++k) {
            float x, y;
            unpk(a1[k], x, y);
            atomicAdd(&S1s[2*k][lane], x);
            atomicAdd(&S1s[2*k+1][lane], y);
            unpk(a2[k], x, y);
            atomicAdd(&S2s[2*k][lane], x);
            atomicAdd(&S2s[2*k+1][lane], y);
        }
        atomicAdd(&rss[lane], rs);
        __syncthreads();

        // ---- stage 2a: per (o,j) stats ----
        const bool last = (it == 2);
        for (int idx = tid; idx < PS_ * B_; idx += NT_) {
            int j = idx >> 5, o = idx & 31;
            float denom = rss[o] + 1e-12f;
            float m  = __fdividef(S1s[j][o], denom);
            float e2 = __fdividef(S2s[j][o], denom);
            float sig = fmaxf(e2 - m * m, 0.0f) + 1e-12f;
            lsg[j][o] = __logf(sig);
            if (last) {
                out[aout_total + ((bb * 512 + o * 16 + j) * OH_ + oy) * OW_ + ox] = m;
            } else {
                float inv = __fdividef(1.0f, sig);
                c1s[j >> 1][o][j & 1] = -m * inv;
                c2s[j >> 1][o][j & 1] = 0.5f * inv;
                c0s[j][o] = 0.5f * m * m * inv;
            }
        }
        __syncthreads();

        // ---- stage 2b: per-o activation (+ global softmax shift) ----
        if (tid < B_) {
            int o = tid;
            float SL = 0.0f, C0 = 0.0f;
            #pragma unroll
            for (int j = 0; j < PS_; ++j) { SL += lsg[j][o]; C0 += c0s[j][o]; }
            float cost = rss[o] * (16.0f * beta_u[o] + 0.5f * SL);
            float x = c_lam[it] * (beta_a[o] - cost);
            float a = 1.0f / (1.0f + __expf(-x));
            if (it == 2) {
                out[((bb * B_ + o) * OH_ + oy) * OW_ + ox] = a;
            } else {
                float base2 = __logf(a) - 0.5f * SL - 8.0f * 0.6086151514f;
                base_s[o] = base2 - C0;
                float mg = base2;
                #pragma unroll
                for (int d = 16; d; d >>= 1)
                    mg = fmaxf(mg, __shfl_xor_sync(0xffffffffu, mg, d));
                if (o == 0) Mglob_s = mg;
            }
        }
        __syncthreads();
    }
}

extern "C" void kernel_launch(void* const* d_in, const int* in_sizes, int n_in,
                              void* d_out, int out_size) {
    const float* a_in  = (const float*)d_in[0];
    const float* pose  = (const float*)d_in[1];
    const float* Wg    = (const float*)d_in[2];
    const float* bu    = (const float*)d_in[3];
    const float* ba    = (const float*)d_in[4];
    float* out = (float*)d_out;

    int batch = in_sizes[0] / (A_ * 16 * 16);   // 8
    int grid = batch * L_;                       // 392

    wprep_kernel<<<(W2SZ + 255) / 256, 256>>>(Wg);
    convcaps_kernel<<<grid, NT_>>>(a_in, pose, bu, ba, out, batch);
}

// round 12
// speedup vs baseline: 1.2097x; 1.1482x over previous
#include <cuda_runtime.h>

#define A_    32
#define B_    32
#define KKA_  288
#define PS_   16
#define OH_   7
#define OW_   7
#define L_    49
#define NW_   4
#define NT_   128
#define W2SZ  (KKA_ * B_ * PS_)   // 147456 floats

typedef unsigned long long u64;

__device__ __constant__ float c_lam[3] = {0.0005f, 0.000975f, 0.00142625f};

// W transposed to [n][k(row)][o][4] so warp reads are coalesced
__device__ __align__(16) float W2g[W2SZ];

__global__ void wprep_kernel(const float* __restrict__ Wg) {
    int idx = blockIdx.x * 256 + threadIdx.x;
    if (idx < W2SZ) {
        int c = idx & 3;
        int o = (idx >> 2) & 31;
        int k = (idx >> 7) & 3;
        int n = idx >> 9;
        W2g[idx] = Wg[(n * 32 + o) * 16 + k * 4 + c];
    }
}

__device__ __forceinline__ u64 b2(float s) {
    u64 r; asm("mov.b64 %0,{%1,%1};" : "=l"(r) : "f"(s)); return r;
}
__device__ __forceinline__ u64 pk2(float x, float y) {
    u64 r; asm("mov.b64 %0,{%1,%2};" : "=l"(r) : "f"(x), "f"(y)); return r;
}
__device__ __forceinline__ u64 fma2(u64 a, u64 b, u64 c) {
    u64 d; asm("fma.rn.f32x2 %0,%1,%2,%3;" : "=l"(d) : "l"(a), "l"(b), "l"(c)); return d;
}
__device__ __forceinline__ u64 mul2(u64 a, u64 b) {
    u64 d; asm("mul.rn.f32x2 %0,%1,%2;" : "=l"(d) : "l"(a), "l"(b)); return d;
}
__device__ __forceinline__ u64 add2(u64 a, u64 b) {
    u64 d; asm("add.rn.f32x2 %0,%1,%2;" : "=l"(d) : "l"(a), "l"(b)); return d;
}
__device__ __forceinline__ void unpk(u64 a, float& x, float& y) {
    asm("mov.b64 {%0,%1},%2;" : "=f"(x), "=f"(y) : "l"(a));
}

// votes for pose row pr against W rows (w0a..w3b): low pair v0, high pair v1
#define VOTES(pr, W, v0, v1)                                                     \
    v0 = mul2(b2(pr.x), W##0a); v0 = fma2(b2(pr.y), W##1a, v0);                  \
    v0 = fma2(b2(pr.z), W##2a, v0); v0 = fma2(b2(pr.w), W##3a, v0);              \
    v1 = mul2(b2(pr.x), W##0b); v1 = fma2(b2(pr.y), W##1b, v1);                  \
    v1 = fma2(b2(pr.z), W##2b, v1); v1 = fma2(b2(pr.w), W##3b, v1);

__global__ void __launch_bounds__(NT_, 3)
convcaps_kernel(const float* __restrict__ a_in,
                const float* __restrict__ pose,
                const float* __restrict__ beta_u,
                const float* __restrict__ beta_a,
                float* __restrict__ out,
                int batch)
{
    __shared__ __align__(16) float pose_s[KKA_][PS_];   // [n][i*4+m]
    __shared__ float au_s[KKA_];
    __shared__ float S1s[PS_][B_];                      // [j][o]
    __shared__ float S2s[PS_][B_];
    __shared__ float rss[B_];
    __shared__ __align__(8) float c1s[8][B_][2];        // [jp][o][j&1] : -mu/sig
    __shared__ __align__(8) float c2s[8][B_][2];        // 0.5/sig
    __shared__ float lsg[PS_][B_];                      // log(sigma^2)
    __shared__ float c0s[PS_][B_];                      // 0.5*mu^2/sig
    __shared__ float base_s[B_];                        // per-o constant for ln_ap
    __shared__ float Mglob_s;                           // global softmax shift

    const int site = blockIdx.x;
    const int bb = site / L_;
    const int l  = site - bb * L_;
    const int oy = l / OW_, ox = l - oy * OW_;
    const int tid = threadIdx.x;
    const int wid = tid >> 5, lane = tid & 31;
    const int aout_total = batch * B_ * L_;

    // ---- load pose window (288 x 16) and activations (288) ----
    for (int idx = tid; idx < KKA_ * PS_; idx += NT_) {
        int n = idx >> 4, s = idx & 15;
        int p = n >> 5, a = n & 31;
        int ki = p / 3, kj = p - 3 * ki;
        pose_s[n][s] = pose[((bb * 512 + a * 16 + s) * 16 + 2 * oy + ki) * 16 + 2 * ox + kj];
    }
    for (int n = tid; n < KKA_; n += NT_) {
        int p = n >> 5, a = n & 31;
        int ki = p / 3, kj = p - 3 * ki;
        au_s[n] = a_in[((bb * 32 + a) * 16 + 2 * oy + ki) * 16 + 2 * ox + kj];
    }
    __syncthreads();

    const u64* c1p = (const u64*)c1s;
    const u64* c2p = (const u64*)c2s;

    for (int it = 0; it < 3; ++it) {
        for (int idx = tid; idx < PS_ * B_; idx += NT_) {
            ((float*)S1s)[idx] = 0.0f;
            ((float*)S2s)[idx] = 0.0f;
        }
        if (tid < B_) rss[tid] = 0.0f;
        __syncthreads();

        u64 a1[8], a2[8];
        #pragma unroll
        for (int k = 0; k < 8; ++k) { a1[k] = 0ull; a2[k] = 0ull; }
        float rs = 0.0f;

        if (it == 0) {
            #pragma unroll 2
            for (int n = wid; n < KKA_; n += NW_) {
                const float4* wf = (const float4*)(W2g + n * 512);
                float4 q0 = wf[lane], q1 = wf[32 + lane], q2 = wf[64 + lane], q3 = wf[96 + lane];
                u64 wa0a = pk2(q0.x, q0.y), wa0b = pk2(q0.z, q0.w);
                u64 wa1a = pk2(q1.x, q1.y), wa1b = pk2(q1.z, q1.w);
                u64 wa2a = pk2(q2.x, q2.y), wa2b = pk2(q2.z, q2.w);
                u64 wa3a = pk2(q3.x, q3.y), wa3b = pk2(q3.z, q3.w);
                float au = au_s[n];
                u64 au2 = b2(au);
                rs += au;
                const float4* prp = (const float4*)pose_s[n];
                #pragma unroll
                for (int i = 0; i < 4; ++i) {
                    float4 pr = prp[i];
                    u64 v0, v1;
                    VOTES(pr, wa, v0, v1);
                    u64 u0 = mul2(au2, v0);
                    a1[2*i]   = add2(a1[2*i], u0);   a2[2*i]   = fma2(u0, v0, a2[2*i]);
                    u64 u1 = mul2(au2, v1);
                    a1[2*i+1] = add2(a1[2*i+1], u1); a2[2*i+1] = fma2(u1, v1, a2[2*i+1]);
                }
            }
        } else {
            const float bm = base_s[lane] - Mglob_s;   // base - Mglob folded
            // per-o coefficients in registers (invariant over n)
            u64 cc1[8], cc2[8];
            #pragma unroll
            for (int k = 0; k < 8; ++k) {
                cc1[k] = c1p[k * B_ + lane];
                cc2[k] = c2p[k * B_ + lane];
            }
            // 3-way interleave; v transient (recomputed in phase B from live W regs)
            #pragma unroll 1
            for (int n = wid; n < KKA_; n += 3 * NW_) {
                const int nB = n + NW_, nC = n + 2 * NW_;
                const float4* wfA = (const float4*)(W2g + n  * 512);
                const float4* wfB = (const float4*)(W2g + nB * 512);
                const float4* wfC = (const float4*)(W2g + nC * 512);
                // front-batch all 12 W loads
                float4 qa0 = wfA[lane], qa1 = wfA[32+lane], qa2 = wfA[64+lane], qa3 = wfA[96+lane];
                float4 qb0 = wfB[lane], qb1 = wfB[32+lane], qb2 = wfB[64+lane], qb3 = wfB[96+lane];
                float4 qc0 = wfC[lane], qc1 = wfC[32+lane], qc2 = wfC[64+lane], qc3 = wfC[96+lane];

                u64 wa0a = pk2(qa0.x,qa0.y), wa0b = pk2(qa0.z,qa0.w);
                u64 wa1a = pk2(qa1.x,qa1.y), wa1b = pk2(qa1.z,qa1.w);
                u64 wa2a = pk2(qa2.x,qa2.y), wa2b = pk2(qa2.z,qa2.w);
                u64 wa3a = pk2(qa3.x,qa3.y), wa3b = pk2(qa3.z,qa3.w);
                u64 wb0a = pk2(qb0.x,qb0.y), wb0b = pk2(qb0.z,qb0.w);
                u64 wb1a = pk2(qb1.x,qb1.y), wb1b = pk2(qb1.z,qb1.w);
                u64 wb2a = pk2(qb2.x,qb2.y), wb2b = pk2(qb2.z,qb2.w);
                u64 wb3a = pk2(qb3.x,qb3.y), wb3b = pk2(qb3.z,qb3.w);
                u64 wc0a = pk2(qc0.x,qc0.y), wc0b = pk2(qc0.z,qc0.w);
                u64 wc1a = pk2(qc1.x,qc1.y), wc1b = pk2(qc1.z,qc1.w);
                u64 wc2a = pk2(qc2.x,qc2.y), wc2b = pk2(qc2.z,qc2.w);
                u64 wc3a = pk2(qc3.x,qc3.y), wc3b = pk2(qc3.z,qc3.w);

                const float4* prA = (const float4*)pose_s[n];
                const float4* prB = (const float4*)pose_s[nB];
                const float4* prC = (const float4*)pose_s[nC];

                // phase A: Mahalanobis with transient votes, 3 chains
                u64 aAx = 0ull, aAy = 0ull, aBx = 0ull, aBy = 0ull, aCx = 0ull, aCy = 0ull;
                #pragma unroll
                for (int i = 0; i < 4; ++i) {
                    float4 pa = prA[i], pb = prB[i], pc = prC[i];
                    u64 v0, v1;
                    VOTES(pa, wa, v0, v1);
                    aAx = fma2(v0, cc1[2*i], aAx);   aAx = fma2(mul2(v0,v0), cc2[2*i], aAx);
                    aAy = fma2(v1, cc1[2*i+1], aAy); aAy = fma2(mul2(v1,v1), cc2[2*i+1], aAy);
                    VOTES(pb, wb, v0, v1);
                    aBx = fma2(v0, cc1[2*i], aBx);   aBx = fma2(mul2(v0,v0), cc2[2*i], aBx);
                    aBy = fma2(v1, cc1[2*i+1], aBy); aBy = fma2(mul2(v1,v1), cc2[2*i+1], aBy);
                    VOTES(pc, wc, v0, v1);
                    aCx = fma2(v0, cc1[2*i], aCx);   aCx = fma2(mul2(v0,v0), cc2[2*i], aCx);
                    aCy = fma2(v1, cc1[2*i+1], aCy); aCy = fma2(mul2(v1,v1), cc2[2*i+1], aCy);
                }
                float x0, y0, x1, y1;
                unpk(aAx, x0, y0); unpk(aAy, x1, y1);
                float tA = bm - ((x0 + y0) + (x1 + y1));
                unpk(aBx, x0, y0); unpk(aBy, x1, y1);
                float tB = bm - ((x0 + y0) + (x1 + y1));
                unpk(aCx, x0, y0); unpk(aCy, x1, y1);
                float tC = bm - ((x0 + y0) + (x1 + y1));

                float eA = __expf(tA), eB = __expf(tB), eC = __expf(tC);
                float sA = eA, sB = eB, sC = eC;
                #pragma unroll
                for (int d = 16; d; d >>= 1) {
                    sA += __shfl_xor_sync(0xffffffffu, sA, d);
                    sB += __shfl_xor_sync(0xffffffffu, sB, d);
                    sC += __shfl_xor_sync(0xffffffffu, sC, d);
                }
                sA = fmaxf(sA, 1e-37f);
                sB = fmaxf(sB, 1e-37f);
                sC = fmaxf(sC, 1e-37f);
                float raA = eA * __fdividef(au_s[n],  sA);
                float raB = eB * __fdividef(au_s[nB], sB);
                float raC = eC * __fdividef(au_s[nC], sC);
                rs += raA + raB + raC;
                u64 rA2 = b2(raA), rB2 = b2(raB), rC2 = b2(raC);

                // phase B: recompute votes (W regs still live), accumulate moments
                #pragma unroll
                for (int i = 0; i < 4; ++i) {
                    float4 pa = prA[i], pb = prB[i], pc = prC[i];
                    u64 v0, v1, u;
                    VOTES(pa, wa, v0, v1);
                    u = mul2(rA2, v0); a1[2*i]   = add2(a1[2*i], u);   a2[2*i]   = fma2(u, v0, a2[2*i]);
                    u = mul2(rA2, v1); a1[2*i+1] = add2(a1[2*i+1], u); a2[2*i+1] = fma2(u, v1, a2[2*i+1]);
                    VOTES(pb, wb, v0, v1);
                    u = mul2(rB2, v0); a1[2*i]   = add2(a1[2*i], u);   a2[2*i]   = fma2(u, v0, a2[2*i]);
                    u = mul2(rB2, v1); a1[2*i+1] = add2(a1[2*i+1], u); a2[2*i+1] = fma2(u, v1, a2[2*i+1]);
                    VOTES(pc, wc, v0, v1);
                    u = mul2(rC2, v0); a1[2*i]   = add2(a1[2*i], u);   a2[2*i]   = fma2(u, v0, a2[2*i]);
                    u = mul2(rC2, v1); a1[2*i+1] = add2(a1[2*i+1], u); a2[2*i+1] = fma2(u, v1, a2[2*i+1]);
                }
            }
        }

        #pragma unroll
        for (int k = 0; k < 8; ++k) {
            float x, y;
            unpk(a1[k], x, y);
            atomicAdd(&S1s[2*k][lane], x);
            atomicAdd(&S1s[2*k+1][lane], y);
            unpk(a2[k], x, y);
            atomicAdd(&S2s[2*k][lane], x);
            atomicAdd(&S2s[2*k+1][lane], y);
        }
        atomicAdd(&rss[lane], rs);
        __syncthreads();

        // ---- stage 2a: per (o,j) stats ----
        const bool last = (it == 2);
        for (int idx = tid; idx < PS_ * B_; idx += NT_) {
            int j = idx >> 5, o = idx & 31;
            float denom = rss[o] + 1e-12f;
            float m  = __fdividef(S1s[j][o], denom);
            float e2 = __fdividef(S2s[j][o], denom);
            float sig = fmaxf(e2 - m * m, 0.0f) + 1e-12f;
            lsg[j][o] = __logf(sig);
            if (last) {
                out[aout_total + ((bb * 512 + o * 16 + j) * OH_ + oy) * OW_ + ox] = m;
            } else {
                float inv = __fdividef(1.0f, sig);
                c1s[j >> 1][o][j & 1] = -m * inv;
                c2s[j >> 1][o][j & 1] = 0.5f * inv;
                c0s[j][o] = 0.5f * m * m * inv;
            }
        }
        __syncthreads();

        // ---- stage 2b: per-o activation (+ global softmax shift) ----
        if (tid < B_) {
            int o = tid;
            float SL = 0.0f, C0 = 0.0f;
            #pragma unroll
            for (int j = 0; j < PS_; ++j) { SL += lsg[j][o]; C0 += c0s[j][o]; }
            float cost = rss[o] * (16.0f * beta_u[o] + 0.5f * SL);
            float x = c_lam[it] * (beta_a[o] - cost);
            float a = 1.0f / (1.0f + __expf(-x));
            if (it == 2) {
                out[((bb * B_ + o) * OH_ + oy) * OW_ + ox] = a;
            } else {
                float base2 = __logf(a) - 0.5f * SL - 8.0f * 0.6086151514f;
                base_s[o] = base2 - C0;
                float mg = base2;
                #pragma unroll
                for (int d = 16; d; d >>= 1)
                    mg = fmaxf(mg, __shfl_xor_sync(0xffffffffu, mg, d));
                if (o == 0) Mglob_s = mg;
            }
        }
        __syncthreads();
    }
}

extern "C" void kernel_launch(void* const* d_in, const int* in_sizes, int n_in,
                              void* d_out, int out_size) {
    const float* a_in  = (const float*)d_in[0];
    const float* pose  = (const float*)d_in[1];
    const float* Wg    = (const float*)d_in[2];
    const float* bu    = (const float*)d_in[3];
    const float* ba    = (const float*)d_in[4];
    float* out = (float*)d_out;

    int batch = in_sizes[0] / (A_ * 16 * 16);   // 8
    int grid = batch * L_;                       // 392

    wprep_kernel<<<(W2SZ + 255) / 256, 256>>>(Wg);
    convcaps_kernel<<<grid, NT_>>>(a_in, pose, bu, ba, out, batch);
}